// round 3
// baseline (speedup 1.0000x reference)
#include <cuda_runtime.h>
#include <cstdint>

#define B_  512
#define C_  6
#define T_  77
#define D_  512
#define LI_ 193

#define OFF_GT 0
#define OFF_GI (B_ * D_)
#define OFF_LT (2 * B_ * D_)
#define OFF_LS (2 * B_ * D_ + B_ * C_ * D_)

#define T_SPLIT 39

// packed f32x2 add: out = a + b (two fp32 lanes in one 64-bit reg)
#define ADDX2(out, a, b) \
    asm("add.rn.f32x2 %0, %1, %2;" : "=l"(out) : "l"(a), "l"(b))

__global__ __launch_bounds__(256, 4)
void clip_fused_kernel(const float* __restrict__ image_features,   // [B, LI, D]
                       const float* __restrict__ text_features,    // [B, T, D]
                       const float* __restrict__ logit_scale,      // [1]
                       const int*   __restrict__ captions,         // [B, T]
                       const int*   __restrict__ noun_chunk_mask,  // [B, C, T]
                       float* __restrict__ out)
{
    const int b    = blockIdx.x;
    const int tid  = threadIdx.x;
    const int half = tid >> 7;      // 0 or 1
    const int col  = tid & 127;     // float4 (=ulonglong2) column within D

    __shared__ int        s_mask[T_];        // bit c set if mask[b,c,t] != 0
    __shared__ int        s_val[128];
    __shared__ int        s_idx[128];
    __shared__ ulonglong2 s_acc[2][C_][128]; // partial packed sums per half

    // ---- Stage packed noun_chunk_mask + caption values ----
    if (tid < T_) {
        int pack = 0;
        const int* mrow = noun_chunk_mask + (size_t)b * C_ * T_ + tid;
        #pragma unroll
        for (int c = 0; c < C_; ++c)
            if (mrow[c * T_] != 0) pack |= (1 << c);
        s_mask[tid] = pack;
        s_val[tid]  = captions[(size_t)b * T_ + tid];
        s_idx[tid]  = tid;
    } else if (tid < 128) {
        s_val[tid] = INT32_MIN;
        s_idx[tid] = T_;
    }

    // global_image [B, D] = image_features[b, 0, :] — issue early for MLP overlap
    if (half) {
        float4 gi = reinterpret_cast<const float4*>(
            image_features + (size_t)b * LI_ * D_)[col];
        reinterpret_cast<float4*>(out + OFF_GI + (size_t)b * D_)[col] = gi;
    }
    __syncthreads();

    // ---- Argmax reduce on first 128 threads (first occurrence on ties) ----
    #pragma unroll
    for (int s = 64; s > 0; s >>= 1) {
        if (tid < s) {
            int v2 = s_val[tid + s], i2 = s_idx[tid + s];
            int v1 = s_val[tid],     i1 = s_idx[tid];
            if (v2 > v1 || (v2 == v1 && i2 < i1)) {
                s_val[tid] = v2;
                s_idx[tid] = i2;
            }
        }
        __syncthreads();
    }
    const int eot = s_idx[0];

    // ---- Stream this half's T range; packed-f32x2 masked accumulation ----
    const int t0 = half ? T_SPLIT : 0;
    const int t1 = half ? T_      : T_SPLIT;

    const ulonglong2* trow = reinterpret_cast<const ulonglong2*>(
        text_features + (size_t)b * T_ * D_) + col;   // [T][D/4]

    unsigned long long aL[C_], aH[C_];
    #pragma unroll
    for (int c = 0; c < C_; ++c) { aL[c] = 0ull; aH[c] = 0ull; }

    #pragma unroll 8
    for (int t = t0; t < t1; ++t) {
        ulonglong2 x = trow[t * (D_ / 4)];
        const int pack = s_mask[t];
        #pragma unroll
        for (int c = 0; c < C_; ++c) {
            if (pack & (1 << c)) {
                ADDX2(aL[c], aL[c], x.x);
                ADDX2(aH[c], aH[c], x.y);
            }
        }
    }

    // global_text [B, D]: one post-loop gather (row is hot in L1/L2)
    if (half == 0) {
        ulonglong2 g = trow[eot * (D_ / 4)];
        reinterpret_cast<ulonglong2*>(out + OFF_GT + (size_t)b * D_)[col] = g;
    }

    // ---- Exchange partials via smem; finalize 3 channels per half ----
    #pragma unroll
    for (int c = 0; c < C_; ++c) {
        ulonglong2 v; v.x = aL[c]; v.y = aH[c];
        s_acc[half][c][col] = v;
    }
    __syncthreads();

    const float inv_T = 1.0f / (float)T_;
    float4* lt = reinterpret_cast<float4*>(out + OFF_LT + (size_t)b * C_ * D_) + col;

    const int c0 = half * (C_ / 2);
    #pragma unroll
    for (int k = 0; k < C_ / 2; ++k) {
        const int c = c0 + k;
        ulonglong2 p0 = s_acc[0][c][col];
        ulonglong2 p1 = s_acc[1][c][col];
        unsigned long long sL, sH;
        ADDX2(sL, p0.x, p1.x);
        ADDX2(sH, p0.y, p1.y);
        float2 lo = *reinterpret_cast<float2*>(&sL);
        float2 hi = *reinterpret_cast<float2*>(&sH);
        float4 r;
        r.x = lo.x * inv_T; r.y = lo.y * inv_T;
        r.z = hi.x * inv_T; r.w = hi.y * inv_T;
        lt[c * (D_ / 4)] = r;
    }

    if (b == 0 && tid == 0) {
        out[OFF_LS] = logit_scale[0];
    }
}

extern "C" void kernel_launch(void* const* d_in, const int* in_sizes, int n_in,
                              void* d_out, int out_size)
{
    const float* image_features  = (const float*)d_in[0];
    const float* text_features   = (const float*)d_in[1];
    const float* logit_scale     = (const float*)d_in[2];
    const int*   captions        = (const int*)d_in[3];
    const int*   noun_chunk_mask = (const int*)d_in[4];
    float* out = (float*)d_out;

    clip_fused_kernel<<<B_, 256>>>(image_features, text_features, logit_scale,
                                   captions, noun_chunk_mask, out);
}

// round 4
// speedup vs baseline: 1.0802x; 1.0802x over previous
#include <cuda_runtime.h>
#include <cstdint>

#define B_  512
#define C_  6
#define T_  77
#define D_  512
#define LI_ 193

#define OFF_GT 0
#define OFF_GI (B_ * D_)
#define OFF_LT (2 * B_ * D_)
#define OFF_LS (2 * B_ * D_ + B_ * C_ * D_)

#define T_SPLIT 39

// One CTA per batch. 256 threads = two halves of the T range;
// each thread owns 4 contiguous d's (float4 column col = tid & 127).
__global__ __launch_bounds__(256, 3)
void clip_fused_kernel(const float* __restrict__ image_features,   // [B, LI, D]
                       const float* __restrict__ text_features,    // [B, T, D]
                       const float* __restrict__ logit_scale,      // [1]
                       const int*   __restrict__ captions,         // [B, T]
                       const int*   __restrict__ noun_chunk_mask,  // [B, C, T]
                       float* __restrict__ out)
{
    const int b    = blockIdx.x;
    const int tid  = threadIdx.x;
    const int half = tid >> 7;      // 0 or 1
    const int col  = tid & 127;     // float4 column within D

    __shared__ int    s_mask[T_];        // bit c set if mask[b,c,t] != 0
    __shared__ int    s_val[T_];         // caption values for argmax
    __shared__ int    s_eot;
    __shared__ float4 s_acc[2][C_][128]; // partial sums per half

    // ---- Stage packed noun_chunk_mask + caption values ----
    if (tid < T_) {
        int pack = 0;
        const int* mrow = noun_chunk_mask + (size_t)b * C_ * T_ + tid;
        #pragma unroll
        for (int c = 0; c < C_; ++c)
            if (mrow[c * T_] != 0) pack |= (1 << c);
        s_mask[tid] = pack;
        s_val[tid]  = captions[(size_t)b * T_ + tid];
    }

    // global_image [B, D] = image_features[b, 0, :] — independent, issue early
    if (half) {
        float4 gi = reinterpret_cast<const float4*>(
            image_features + (size_t)b * LI_ * D_)[col];
        reinterpret_cast<float4*>(out + OFF_GI + (size_t)b * D_)[col] = gi;
    }
    __syncthreads();   // mask + captions staged

    // ---- Stream this half's T range; masked float4 accumulation ----
    const int t0 = half ? T_SPLIT : 0;
    const int t1 = half ? T_      : T_SPLIT;

    const float4* trow = reinterpret_cast<const float4*>(
        text_features + (size_t)b * T_ * D_) + col;  // [T][D/4]

    float4 acc[C_];
    #pragma unroll
    for (int c = 0; c < C_; ++c) acc[c] = make_float4(0.f, 0.f, 0.f, 0.f);

    #pragma unroll 8
    for (int t = t0; t < t1; ++t) {
        float4 x = trow[t * (D_ / 4)];
        const int pack = s_mask[t];
        #pragma unroll
        for (int c = 0; c < C_; ++c) {
            if (pack & (1 << c)) {
                acc[c].x += x.x; acc[c].y += x.y;
                acc[c].z += x.z; acc[c].w += x.w;
            }
        }
    }

    // ---- Write partials; warp 0 computes argmax concurrently ----
    #pragma unroll
    for (int c = 0; c < C_; ++c) s_acc[half][c][col] = acc[c];

    if (tid < 32) {
        // lane l scans t = l, l+32, l+64 ascending: strict > keeps first occurrence
        int v = (tid < T_) ? s_val[tid] : INT32_MIN;
        int i = tid;
        #pragma unroll
        for (int k = 32; k < 96; k += 32) {
            int t = tid + k;
            if (t < T_) {
                int v2 = s_val[t];
                if (v2 > v) { v = v2; i = t; }
            }
        }
        // butterfly reduce with first-occurrence tie-break
        #pragma unroll
        for (int off = 16; off > 0; off >>= 1) {
            int v2 = __shfl_xor_sync(0xFFFFFFFFu, v, off);
            int i2 = __shfl_xor_sync(0xFFFFFFFFu, i, off);
            if (v2 > v || (v2 == v && i2 < i)) { v = v2; i = i2; }
        }
        if (tid == 0) s_eot = i;
    }
    __syncthreads();   // partials + eot ready

    // global_text [B, D]: one gather of a row this CTA just streamed (L1/L2 hot)
    if (half == 0) {
        float4 g = trow[s_eot * (D_ / 4)];
        reinterpret_cast<float4*>(out + OFF_GT + (size_t)b * D_)[col] = g;
    }

    // ---- Combine partials; each half finalizes 3 channels ----
    const float inv_T = 1.0f / (float)T_;
    float4* lt = reinterpret_cast<float4*>(out + OFF_LT + (size_t)b * C_ * D_) + col;

    const int c0 = half * (C_ / 2);
    #pragma unroll
    for (int k = 0; k < C_ / 2; ++k) {
        const int c = c0 + k;
        float4 a0 = s_acc[0][c][col];
        float4 a1 = s_acc[1][c][col];
        float4 r;
        r.x = (a0.x + a1.x) * inv_T;
        r.y = (a0.y + a1.y) * inv_T;
        r.z = (a0.z + a1.z) * inv_T;
        r.w = (a0.w + a1.w) * inv_T;
        lt[c * (D_ / 4)] = r;
    }

    if (b == 0 && tid == 0) {
        out[OFF_LS] = logit_scale[0];
    }
}

extern "C" void kernel_launch(void* const* d_in, const int* in_sizes, int n_in,
                              void* d_out, int out_size)
{
    const float* image_features  = (const float*)d_in[0];
    const float* text_features   = (const float*)d_in[1];
    const float* logit_scale     = (const float*)d_in[2];
    const int*   captions        = (const int*)d_in[3];
    const int*   noun_chunk_mask = (const int*)d_in[4];
    float* out = (float*)d_out;

    clip_fused_kernel<<<B_, 256>>>(image_features, text_features, logit_scale,
                                   captions, noun_chunk_mask, out);
}